// round 3
// baseline (speedup 1.0000x reference)
#include <cuda_runtime.h>
#include <math_constants.h>

// Softmax over last dim: x shape (16, 64, 256, 256) -> softmax over flattened
// 256*256 = 65536 per (b, c) row. 1024 rows total, fp32 in/out.
//
// Strategy: one 1024-thread CTA per row. Pass 1: vectorized float4 read,
// online (max, sum) per thread, warp shuffle reduce, smem cross-warp reduce.
// Pass 2: re-read row (should be L2-resident: 2 CTAs/SM * 148 * 256KB = 74MB
// < 126MB L2), write exp(x - max) * inv_sum.

#define ROW_LEN   65536
#define ROW_LEN4  (ROW_LEN / 4)   // 16384 float4 per row
#define NTHREADS  1024
#define NWARPS    (NTHREADS / 32)

__global__ __launch_bounds__(NTHREADS, 2)
void softmax_row_kernel(const float* __restrict__ x, float* __restrict__ out) {
    const int row = blockIdx.x;
    const float4* __restrict__ xr = reinterpret_cast<const float4*>(x) + (size_t)row * ROW_LEN4;
    float4* __restrict__ outr     = reinterpret_cast<float4*>(out)     + (size_t)row * ROW_LEN4;

    const int tid  = threadIdx.x;
    const int lane = tid & 31;
    const int wid  = tid >> 5;

    // ---- Pass 1: online (max, sum) over this thread's strided elements ----
    float lmax = -CUDART_INF_F;
    float lsum = 0.0f;

    #pragma unroll 4
    for (int i = tid; i < ROW_LEN4; i += NTHREADS) {
        float4 v = xr[i];
        float m = fmaxf(fmaxf(v.x, v.y), fmaxf(v.z, v.w));
        if (m > lmax) {
            lsum *= __expf(lmax - m);
            lmax = m;
        }
        lsum += __expf(v.x - lmax) + __expf(v.y - lmax)
              + __expf(v.z - lmax) + __expf(v.w - lmax);
    }

    // ---- Warp reduce (max, sum) ----
    #pragma unroll
    for (int off = 16; off > 0; off >>= 1) {
        float om = __shfl_xor_sync(0xFFFFFFFFu, lmax, off);
        float os = __shfl_xor_sync(0xFFFFFFFFu, lsum, off);
        float nm = fmaxf(lmax, om);
        lsum = lsum * __expf(lmax - nm) + os * __expf(om - nm);
        lmax = nm;
    }

    // ---- Cross-warp reduce via shared memory ----
    __shared__ float smax[NWARPS];
    __shared__ float ssum[NWARPS];
    __shared__ float s_bcast[2];  // [0] = row max, [1] = inv row sum

    if (lane == 0) {
        smax[wid] = lmax;
        ssum[wid] = lsum;
    }
    __syncthreads();

    if (wid == 0) {
        float m = (lane < NWARPS) ? smax[lane] : -CUDART_INF_F;
        float s = (lane < NWARPS) ? ssum[lane] : 0.0f;
        #pragma unroll
        for (int off = 16; off > 0; off >>= 1) {
            float om = __shfl_xor_sync(0xFFFFFFFFu, m, off);
            float os = __shfl_xor_sync(0xFFFFFFFFu, s, off);
            float nm = fmaxf(m, om);
            s = s * __expf(m - nm) + os * __expf(om - nm);
            m = nm;
        }
        if (lane == 0) {
            s_bcast[0] = m;
            s_bcast[1] = 1.0f / s;
        }
    }
    __syncthreads();

    const float rmax = s_bcast[0];
    const float rinv = s_bcast[1];

    // ---- Pass 2: normalize (row re-read should hit L2) ----
    #pragma unroll 4
    for (int i = tid; i < ROW_LEN4; i += NTHREADS) {
        float4 v = xr[i];
        float4 o;
        o.x = __expf(v.x - rmax) * rinv;
        o.y = __expf(v.y - rmax) * rinv;
        o.z = __expf(v.z - rmax) * rinv;
        o.w = __expf(v.w - rmax) * rinv;
        outr[i] = o;
    }
}

extern "C" void kernel_launch(void* const* d_in, const int* in_sizes, int n_in,
                              void* d_out, int out_size) {
    const float* x = (const float*)d_in[0];
    float* out = (float*)d_out;
    // 16 * 64 = 1024 rows of 65536 elements
    const int n_rows = in_sizes[0] / ROW_LEN;
    softmax_row_kernel<<<n_rows, NTHREADS>>>(x, out);
}